// round 4
// baseline (speedup 1.0000x reference)
#include <cuda_runtime.h>
#include <cuda_bf16.h>

// Problem constants
#define Wd 192
#define Hd 192
#define Dd 128
#define Bd 2
#define TX 32
#define TY 8
#define DCHUNK 16
#define SROW 34           // (TX+2) columns per smem row
#define PLANE ((TY + 2) * SROW)   // 10 * 34 = 340 floats per z-plane

// exp2 via MUFU.EX2 directly (independent of nvcc fast-math flags)
__device__ __forceinline__ float ex2f(float x) {
    float y;
    asm("ex2.approx.ftz.f32 %0, %1;" : "=f"(y) : "f"(x));
    return y;
}

__global__ __launch_bounds__(TX * TY)
void bilat3d_kernel(const float* __restrict__ in, float* __restrict__ out) {
    __shared__ float sm[3 * PLANE];

    const int tx  = threadIdx.x;
    const int ty  = threadIdx.y;
    const int tid = ty * TX + tx;
    const int w0  = blockIdx.x * TX;
    const int h0  = blockIdx.y * TY;
    const int bz  = blockIdx.z;
    const int b      = bz / (Dd / DCHUNK);
    const int dstart = (bz % (Dd / DCHUNK)) * DCHUNK;

    const float* base = in + (size_t)b * Dd * Hd * Wd;

    // Load one z-plane (with replicate-padded halo) into smem slot.
    auto loadPlane = [&](int d, int slot) {
        d = min(max(d, 0), Dd - 1);
        const float* p = base + (size_t)d * Hd * Wd;
        #pragma unroll
        for (int i = tid; i < PLANE; i += TX * TY) {
            int r  = i / SROW;
            int c  = i - r * SROW;
            int gh = min(max(h0 + r - 1, 0), Hd - 1);
            int gw = min(max(w0 + c - 1, 0), Wd - 1);
            sm[slot * PLANE + i] = p[gh * Wd + gw];
        }
    };

    // Preload planes d-1 and d for the first chunk element.
    loadPlane(dstart - 1, 0);
    loadPlane(dstart,     1);
    int s0 = 0, s1 = 1, s2 = 2;

    // Combined weight: sw(dist) * exp(-diff^2 / (2*sigma_r^2))
    //   = exp2( diff^2 * (-log2e / (2*1.2^2))  +  dist * (-log2e / (2*120^2)) )
    const float KR = -0.50093579f;           // -log2(e) / 2.88

    for (int dd = 0; dd < DCHUNK; ++dd) {
        loadPlane(dstart + dd + 1, s2);
        __syncthreads();

        const float c = sm[s1 * PLANE + (ty + 1) * SROW + (tx + 1)];
        float num = 0.0f, den = 0.0f;

        #pragma unroll
        for (int zi = 0; zi < 3; ++zi) {
            const int sl = (zi == 0 ? s0 : (zi == 1 ? s1 : s2));
            #pragma unroll
            for (int yi = 0; yi < 3; ++yi) {
                #pragma unroll
                for (int xi = 0; xi < 3; ++xi) {
                    float n  = sm[sl * PLANE + (ty + yi) * SROW + (tx + xi)];
                    float df = n - c;
                    // compile-time spatial distance^2 in {0,1,2,3}
                    const int dist = (zi - 1) * (zi - 1) + (yi - 1) * (yi - 1)
                                   + (xi - 1) * (xi - 1);
                    const float KS = (float)dist * -5.0093579e-5f; // -dist*log2e/28800
                    float arg = fmaf(df * df, KR, KS);
                    float wgt = ex2f(arg);
                    num = fmaf(wgt, n, num);
                    den += wgt;
                }
            }
        }

        const int d = dstart + dd;
        out[((size_t)(b * Dd + d) * Hd + (h0 + ty)) * Wd + (w0 + tx)] =
            __fdividef(num, den);   // den >= 1 always (center weight = 1)

        __syncthreads();            // protect slot reuse before next load
        int t = s0; s0 = s1; s1 = s2; s2 = t;
    }
}

extern "C" void kernel_launch(void* const* d_in, const int* in_sizes, int n_in,
                              void* d_out, int out_size) {
    const float* vol = (const float*)d_in[0];
    float* out = (float*)d_out;
    dim3 grid(Wd / TX, Hd / TY, Bd * (Dd / DCHUNK));  // 6 x 24 x 16 = 2304 CTAs
    dim3 block(TX, TY);                                // 256 threads
    bilat3d_kernel<<<grid, block>>>(vol, out);
}